// round 1
// baseline (speedup 1.0000x reference)
#include <cuda_runtime.h>
#include <math.h>

#define B_  4
#define T_  4096
#define D_  1024
#define DH_ 64
#define NROW (B_ * T_)

// Scratch for projected Q,K,V (allocation-free rule: __device__ globals)
__device__ float g_Q[NROW * DH_];
__device__ float g_K[NROW * DH_];
__device__ float g_V[NROW * DH_];

// ---------------------------------------------------------------------------
// Kernel 1: QKV projection.  out[row, h] = sum_d x[row, d] * W[d, h]
// Grid: (NROW/64, 3). Block: 256 threads. 64x64 output tile, BK=32 k-chunks.
// ---------------------------------------------------------------------------
__global__ __launch_bounds__(256) void proj_kernel(
    const float* __restrict__ x,
    const float* __restrict__ Wq,
    const float* __restrict__ Wk,
    const float* __restrict__ Wv)
{
    const int tile  = blockIdx.x;          // 64-row tile
    const int which = blockIdx.y;          // 0=Q 1=K 2=V
    const float* W  = (which == 0) ? Wq : (which == 1) ? Wk : Wv;
    float* out      = (which == 0) ? g_Q : (which == 1) ? g_K : g_V;

    __shared__ float xs[64][33];           // 64 rows x 32 k (padded)
    __shared__ float ws[32][DH_];          // 32 k x 64 h

    const int tid = threadIdx.x;
    const int tx = tid & 15, ty = tid >> 4;
    const int r0 = ty * 4, c0 = tx * 4;
    const int row_base = tile * 64;

    float acc[4][4] = {};

    for (int k0 = 0; k0 < D_; k0 += 32) {
        // load x tile: 64x32 floats = 512 float4
        #pragma unroll
        for (int p = tid; p < 512; p += 256) {
            int r = p >> 3, c4 = (p & 7) * 4;
            float4 v = *reinterpret_cast<const float4*>(
                &x[(size_t)(row_base + r) * D_ + k0 + c4]);
            xs[r][c4 + 0] = v.x; xs[r][c4 + 1] = v.y;
            xs[r][c4 + 2] = v.z; xs[r][c4 + 3] = v.w;
        }
        // load W tile: 32x64 floats = 512 float4
        #pragma unroll
        for (int p = tid; p < 512; p += 256) {
            int kr = p >> 4, c4 = (p & 15) * 4;
            float4 v = *reinterpret_cast<const float4*>(
                &W[(size_t)(k0 + kr) * DH_ + c4]);
            ws[kr][c4 + 0] = v.x; ws[kr][c4 + 1] = v.y;
            ws[kr][c4 + 2] = v.z; ws[kr][c4 + 3] = v.w;
        }
        __syncthreads();

        #pragma unroll 8
        for (int kk = 0; kk < 32; kk++) {
            float a[4], b[4];
            #pragma unroll
            for (int i = 0; i < 4; i++) a[i] = xs[r0 + i][kk];
            #pragma unroll
            for (int j = 0; j < 4; j++) b[j] = ws[kk][c0 + j];
            #pragma unroll
            for (int i = 0; i < 4; i++)
                #pragma unroll
                for (int j = 0; j < 4; j++)
                    acc[i][j] = fmaf(a[i], b[j], acc[i][j]);
        }
        __syncthreads();
    }

    #pragma unroll
    for (int i = 0; i < 4; i++)
        #pragma unroll
        for (int j = 0; j < 4; j++)
            out[(size_t)(row_base + r0 + i) * DH_ + c0 + j] = acc[i][j];
}

// ---------------------------------------------------------------------------
// Kernel 2: causal flash attention. 64 queries per block, kv tiles of 64.
// Grid: (T/64, B). Block: 256 threads, 4x4 micro-tiles, online softmax.
// ---------------------------------------------------------------------------
#define SROW 68   // smem row stride (floats): padded, 16B-aligned

__global__ __launch_bounds__(256) void attn_kernel(float* __restrict__ out)
{
    extern __shared__ float sm[];
    float (*Qs)[SROW] = (float(*)[SROW])(sm);
    float (*Ks)[SROW] = (float(*)[SROW])(sm + 64 * SROW);
    float (*Vs)[SROW] = (float(*)[SROW])(sm + 2 * 64 * SROW);
    float (*Ss)[SROW] = (float(*)[SROW])(sm + 3 * 64 * SROW);

    const int b  = blockIdx.y;
    const int qt = gridDim.x - 1 - blockIdx.x;   // heavy tiles first
    const int tid = threadIdx.x;
    const int tx = tid & 15, ty = tid >> 4;
    const int r0 = ty * 4, c0 = tx * 4;
    const float scale = 0.03125f;                // 1024^-0.5

    // load Q tile (64x64)
    const float* Qg = g_Q + (size_t)(b * T_ + qt * 64) * DH_;
    #pragma unroll
    for (int p = tid; p < 1024; p += 256) {
        int r = p >> 4, c4 = (p & 15) * 4;
        float4 v = *reinterpret_cast<const float4*>(&Qg[r * DH_ + c4]);
        Qs[r][c4 + 0] = v.x; Qs[r][c4 + 1] = v.y;
        Qs[r][c4 + 2] = v.z; Qs[r][c4 + 3] = v.w;
    }

    float m[4], l[4], o[4][4];
    #pragma unroll
    for (int i = 0; i < 4; i++) {
        m[i] = -INFINITY; l[i] = 0.f;
        #pragma unroll
        for (int j = 0; j < 4; j++) o[i][j] = 0.f;
    }
    __syncthreads();

    for (int t = 0; t <= qt; t++) {
        // load K,V tiles
        const float* Kg = g_K + (size_t)(b * T_ + t * 64) * DH_;
        const float* Vg = g_V + (size_t)(b * T_ + t * 64) * DH_;
        #pragma unroll
        for (int p = tid; p < 1024; p += 256) {
            int r = p >> 4, c4 = (p & 15) * 4;
            float4 v = *reinterpret_cast<const float4*>(&Kg[r * DH_ + c4]);
            Ks[r][c4 + 0] = v.x; Ks[r][c4 + 1] = v.y;
            Ks[r][c4 + 2] = v.z; Ks[r][c4 + 3] = v.w;
            float4 w = *reinterpret_cast<const float4*>(&Vg[r * DH_ + c4]);
            Vs[r][c4 + 0] = w.x; Vs[r][c4 + 1] = w.y;
            Vs[r][c4 + 2] = w.z; Vs[r][c4 + 3] = w.w;
        }
        __syncthreads();

        // S = Q K^T  (4x4 per thread over k=64)
        float s[4][4] = {};
        #pragma unroll 4
        for (int k4 = 0; k4 < 16; k4++) {
            float4 q4[4], kv4[4];
            #pragma unroll
            for (int i = 0; i < 4; i++)
                q4[i] = *reinterpret_cast<const float4*>(&Qs[r0 + i][k4 * 4]);
            #pragma unroll
            for (int j = 0; j < 4; j++)
                kv4[j] = *reinterpret_cast<const float4*>(&Ks[c0 + j][k4 * 4]);
            #pragma unroll
            for (int i = 0; i < 4; i++)
                #pragma unroll
                for (int j = 0; j < 4; j++) {
                    s[i][j] = fmaf(q4[i].x, kv4[j].x, s[i][j]);
                    s[i][j] = fmaf(q4[i].y, kv4[j].y, s[i][j]);
                    s[i][j] = fmaf(q4[i].z, kv4[j].z, s[i][j]);
                    s[i][j] = fmaf(q4[i].w, kv4[j].w, s[i][j]);
                }
        }

        const bool diag = (t == qt);

        // online softmax per q-row
        #pragma unroll
        for (int i = 0; i < 4; i++) {
            float mt = -INFINITY;
            #pragma unroll
            for (int j = 0; j < 4; j++) {
                float v = s[i][j] * scale;
                if (diag && (c0 + j) > (r0 + i)) v = -1e30f;
                s[i][j] = v;
                mt = fmaxf(mt, v);
            }
            #pragma unroll
            for (int off = 1; off < 16; off <<= 1)
                mt = fmaxf(mt, __shfl_xor_sync(0xffffffffu, mt, off));

            float mn    = fmaxf(m[i], mt);
            float alpha = __expf(m[i] - mn);
            m[i] = mn;

            float rs = 0.f;
            #pragma unroll
            for (int j = 0; j < 4; j++) {
                float p = __expf(s[i][j] - mn);
                s[i][j] = p;
                rs += p;
            }
            #pragma unroll
            for (int off = 1; off < 16; off <<= 1)
                rs += __shfl_xor_sync(0xffffffffu, rs, off);

            l[i] = l[i] * alpha + rs;
            #pragma unroll
            for (int j = 0; j < 4; j++) o[i][j] *= alpha;

            // publish p row-chunk
            *reinterpret_cast<float4*>(&Ss[r0 + i][c0]) =
                make_float4(s[i][0], s[i][1], s[i][2], s[i][3]);
        }
        __syncthreads();

        // O += P V  (4x4 per thread over k=64)
        #pragma unroll 4
        for (int k4 = 0; k4 < 16; k4++) {
            float4 p4[4], v4[4];
            #pragma unroll
            for (int i = 0; i < 4; i++)
                p4[i] = *reinterpret_cast<const float4*>(&Ss[r0 + i][k4 * 4]);
            #pragma unroll
            for (int kk = 0; kk < 4; kk++)
                v4[kk] = *reinterpret_cast<const float4*>(&Vs[k4 * 4 + kk][c0]);
            #pragma unroll
            for (int i = 0; i < 4; i++) {
                o[i][0] = fmaf(p4[i].x, v4[0].x, o[i][0]);
                o[i][1] = fmaf(p4[i].x, v4[0].y, o[i][1]);
                o[i][2] = fmaf(p4[i].x, v4[0].z, o[i][2]);
                o[i][3] = fmaf(p4[i].x, v4[0].w, o[i][3]);
                o[i][0] = fmaf(p4[i].y, v4[1].x, o[i][0]);
                o[i][1] = fmaf(p4[i].y, v4[1].y, o[i][1]);
                o[i][2] = fmaf(p4[i].y, v4[1].z, o[i][2]);
                o[i][3] = fmaf(p4[i].y, v4[1].w, o[i][3]);
                o[i][0] = fmaf(p4[i].z, v4[2].x, o[i][0]);
                o[i][1] = fmaf(p4[i].z, v4[2].y, o[i][1]);
                o[i][2] = fmaf(p4[i].z, v4[2].z, o[i][2]);
                o[i][3] = fmaf(p4[i].z, v4[2].w, o[i][3]);
                o[i][0] = fmaf(p4[i].w, v4[3].x, o[i][0]);
                o[i][1] = fmaf(p4[i].w, v4[3].y, o[i][1]);
                o[i][2] = fmaf(p4[i].w, v4[3].z, o[i][2]);
                o[i][3] = fmaf(p4[i].w, v4[3].w, o[i][3]);
            }
        }
        __syncthreads();   // protect K/V/S before next iteration's loads
    }

    // epilogue: normalize and store
    float* Og = out + (size_t)(b * T_ + qt * 64) * DH_;
    #pragma unroll
    for (int i = 0; i < 4; i++) {
        float inv = 1.0f / l[i];
        #pragma unroll
        for (int j = 0; j < 4; j++)
            Og[(r0 + i) * DH_ + c0 + j] = o[i][j] * inv;
    }
}

// ---------------------------------------------------------------------------
extern "C" void kernel_launch(void* const* d_in, const int* in_sizes, int n_in,
                              void* d_out, int out_size)
{
    const float* x  = (const float*)d_in[0];
    const float* Wq = (const float*)d_in[1];
    const float* Wk = (const float*)d_in[2];
    const float* Wv = (const float*)d_in[3];
    float* out = (float*)d_out;

    // Projection: 256 row-tiles x {Q,K,V}
    dim3 g1(NROW / 64, 3);
    proj_kernel<<<g1, 256>>>(x, Wq, Wk, Wv);

    // Attention
    size_t smem = (size_t)4 * 64 * SROW * sizeof(float);   // 69632 B
    cudaFuncSetAttribute(attn_kernel,
                         cudaFuncAttributeMaxDynamicSharedMemorySize,
                         (int)smem);
    dim3 g2(T_ / 64, B_);
    attn_kernel<<<g2, 256, smem>>>(out);
}

// round 2
// speedup vs baseline: 1.0107x; 1.0107x over previous
#include <cuda_runtime.h>
#include <math.h>

#define B_  4
#define T_  4096
#define D_  1024
#define DH_ 64
#define NROW (B_ * T_)
#define NITEM 256          // 64 q-tiles x 4 batches

__device__ float g_Q[NROW * DH_];
__device__ float g_K[NROW * DH_];
__device__ float g_V[NROW * DH_];
__device__ unsigned int g_ctr;

// ---- packed f32x2 helpers (Blackwell FFMA2 path: ptxas never auto-fuses) ----
#define FMA2(d, a, b) asm("fma.rn.f32x2 %0, %1, %2, %0;" : "+l"(d) : "l"(a), "l"(b))
#define MUL2(d, a, b) asm("mul.rn.f32x2 %0, %1, %2;" : "=l"(d) : "l"(a), "l"(b))

static __device__ __forceinline__ unsigned long long pk2(float a, float b) {
    unsigned long long r;
    asm("mov.b64 %0, {%1, %2};" : "=l"(r) : "f"(a), "f"(b));
    return r;
}
static __device__ __forceinline__ float unpk_sum(unsigned long long v) {
    float lo, hi;
    asm("mov.b64 {%0, %1}, %2;" : "=f"(lo), "=f"(hi) : "l"(v));
    return lo + hi;
}

// ---------------------------------------------------------------------------
// Kernel 1: QKV projection with f32x2.  out[row,h] = sum_d x[row,d]*W[d,h]
// Grid: (NROW/64, 3). Block 256. 64x64 tile, BK=32.
// ---------------------------------------------------------------------------
__global__ __launch_bounds__(256) void proj_kernel(
    const float* __restrict__ x,
    const float* __restrict__ Wq,
    const float* __restrict__ Wk,
    const float* __restrict__ Wv)
{
    const int tile  = blockIdx.x;
    const int which = blockIdx.y;
    const float* W  = (which == 0) ? Wq : (which == 1) ? Wk : Wv;
    float* out      = (which == 0) ? g_Q : (which == 1) ? g_K : g_V;

    __shared__ float xs[64][34];   // stride 34: keeps 8B alignment for u64 loads
    __shared__ float ws[32][DH_];

    const int tid = threadIdx.x;
    const int tx = tid & 15, ty = tid >> 4;
    const int r0 = ty * 4, c0 = tx * 4;
    const int row_base = tile * 64;

    if (tile == 0 && which == 0 && tid == 0) g_ctr = 0;   // reset attn work queue

    unsigned long long acc2[4][4];
    #pragma unroll
    for (int i = 0; i < 4; i++)
        #pragma unroll
        for (int j = 0; j < 4; j++) acc2[i][j] = 0ull;

    for (int k0 = 0; k0 < D_; k0 += 32) {
        #pragma unroll
        for (int p = tid; p < 512; p += 256) {
            int r = p >> 3, c4 = (p & 7) * 4;
            float4 v = *reinterpret_cast<const float4*>(
                &x[(size_t)(row_base + r) * D_ + k0 + c4]);
            xs[r][c4 + 0] = v.x; xs[r][c4 + 1] = v.y;
            xs[r][c4 + 2] = v.z; xs[r][c4 + 3] = v.w;
        }
        #pragma unroll
        for (int p = tid; p < 512; p += 256) {
            int kr = p >> 4, c4 = (p & 15) * 4;
            *reinterpret_cast<float4*>(&ws[kr][c4]) =
                *reinterpret_cast<const float4*>(&W[(size_t)(k0 + kr) * DH_ + c4]);
        }
        __syncthreads();

        #pragma unroll 4
        for (int kp = 0; kp < 16; kp++) {
            unsigned long long a2[4];
            #pragma unroll
            for (int i = 0; i < 4; i++)
                a2[i] = *reinterpret_cast<const unsigned long long*>(&xs[r0 + i][kp * 2]);
            float4 wa = *reinterpret_cast<const float4*>(&ws[kp * 2][c0]);
            float4 wb = *reinterpret_cast<const float4*>(&ws[kp * 2 + 1][c0]);
            unsigned long long b2[4];
            b2[0] = pk2(wa.x, wb.x); b2[1] = pk2(wa.y, wb.y);
            b2[2] = pk2(wa.z, wb.z); b2[3] = pk2(wa.w, wb.w);
            #pragma unroll
            for (int i = 0; i < 4; i++)
                #pragma unroll
                for (int j = 0; j < 4; j++)
                    FMA2(acc2[i][j], a2[i], b2[j]);
        }
        __syncthreads();
    }

    #pragma unroll
    for (int i = 0; i < 4; i++) {
        float4 r;
        r.x = unpk_sum(acc2[i][0]); r.y = unpk_sum(acc2[i][1]);
        r.z = unpk_sum(acc2[i][2]); r.w = unpk_sum(acc2[i][3]);
        *reinterpret_cast<float4*>(&out[(size_t)(row_base + r0 + i) * DH_ + c0]) = r;
    }
}

// ---------------------------------------------------------------------------
// Kernel 2: persistent causal flash attention, f32x2 math, conflict-free smem.
// Work items = (b, qt) pulled heavy-first from atomic counter.
// S-columns owned strided (tx+16j) -> conflict-free K loads & S stores.
// O-columns owned contiguous (tx*4) -> conflict-free V loads & O stores.
// ---------------------------------------------------------------------------
#define SROW 68

__global__ __launch_bounds__(256, 2) void attn_kernel(float* __restrict__ out)
{
    extern __shared__ float sm[];
    float (*Qs)[SROW] = (float(*)[SROW])(sm);
    float (*Ks)[SROW] = (float(*)[SROW])(sm + 64 * SROW);
    float (*Vs)[SROW] = (float(*)[SROW])(sm + 2 * 64 * SROW);
    float (*Ss)[SROW] = (float(*)[SROW])(sm + 3 * 64 * SROW);
    __shared__ int s_item;

    const int tid = threadIdx.x;
    const int tx = tid & 15, ty = tid >> 4;
    const int r0 = ty * 4, c0 = tx * 4;
    const float scale = 0.03125f;   // 1024^-0.5

    for (;;) {
        if (tid == 0) s_item = atomicAdd(&g_ctr, 1);
        __syncthreads();            // also protects smem reuse across items
        const int n = s_item;
        if (n >= NITEM) return;
        const int qt = 63 - (n >> 2);   // heaviest first
        const int b  = n & 3;

        // load Q tile
        const float* Qg = g_Q + (size_t)(b * T_ + qt * 64) * DH_;
        #pragma unroll
        for (int p = tid; p < 1024; p += 256) {
            int r = p >> 4, c4 = (p & 15) * 4;
            float4 v = *reinterpret_cast<const float4*>(&Qg[r * DH_ + c4]);
            Qs[r][c4 + 0] = v.x; Qs[r][c4 + 1] = v.y;
            Qs[r][c4 + 2] = v.z; Qs[r][c4 + 3] = v.w;
        }

        float m[4], l[4];
        unsigned long long o2[4][4];
        #pragma unroll
        for (int i = 0; i < 4; i++) {
            m[i] = -INFINITY; l[i] = 0.f;
            #pragma unroll
            for (int j = 0; j < 4; j++) o2[i][j] = 0ull;
        }
        __syncthreads();

        for (int t = 0; t <= qt; t++) {
            const float* Kg = g_K + (size_t)(b * T_ + t * 64) * DH_;
            const float* Vg = g_V + (size_t)(b * T_ + t * 64) * DH_;
            #pragma unroll
            for (int p = tid; p < 1024; p += 256) {
                int r = p >> 4, c4 = (p & 15) * 4;
                float4 v = *reinterpret_cast<const float4*>(&Kg[r * DH_ + c4]);
                Ks[r][c4 + 0] = v.x; Ks[r][c4 + 1] = v.y;
                Ks[r][c4 + 2] = v.z; Ks[r][c4 + 3] = v.w;
                float4 w = *reinterpret_cast<const float4*>(&Vg[r * DH_ + c4]);
                Vs[r][c4 + 0] = w.x; Vs[r][c4 + 1] = w.y;
                Vs[r][c4 + 2] = w.z; Vs[r][c4 + 3] = w.w;
            }
            __syncthreads();

            // ---- S = Q K^T, packed along dh ----
            unsigned long long s2[4][4];
            #pragma unroll
            for (int i = 0; i < 4; i++)
                #pragma unroll
                for (int j = 0; j < 4; j++) s2[i][j] = 0ull;

            #pragma unroll 4
            for (int k4 = 0; k4 < 16; k4++) {
                ulonglong2 q2[4], k2[4];
                #pragma unroll
                for (int i = 0; i < 4; i++)
                    q2[i] = *reinterpret_cast<const ulonglong2*>(&Qs[r0 + i][k4 * 4]);
                #pragma unroll
                for (int j = 0; j < 4; j++)
                    k2[j] = *reinterpret_cast<const ulonglong2*>(&Ks[tx + 16 * j][k4 * 4]);
                #pragma unroll
                for (int i = 0; i < 4; i++)
                    #pragma unroll
                    for (int j = 0; j < 4; j++) {
                        FMA2(s2[i][j], q2[i].x, k2[j].x);
                        FMA2(s2[i][j], q2[i].y, k2[j].y);
                    }
            }

            const bool diag = (t == qt);

            // ---- online softmax (row owned by 16 lanes sharing ty) ----
            #pragma unroll
            for (int i = 0; i < 4; i++) {
                float sv[4];
                float mt = -INFINITY;
                #pragma unroll
                for (int j = 0; j < 4; j++) {
                    float v = unpk_sum(s2[i][j]) * scale;
                    if (diag && (tx + 16 * j) > (r0 + i)) v = -1e30f;
                    sv[j] = v;
                    mt = fmaxf(mt, v);
                }
                #pragma unroll
                for (int off = 1; off < 16; off <<= 1)
                    mt = fmaxf(mt, __shfl_xor_sync(0xffffffffu, mt, off));

                float mn    = fmaxf(m[i], mt);
                float alpha = __expf(m[i] - mn);
                m[i] = mn;

                float rs = 0.f;
                #pragma unroll
                for (int j = 0; j < 4; j++) {
                    float p = __expf(sv[j] - mn);
                    Ss[r0 + i][tx + 16 * j] = p;      // conflict-free scattered STS
                    rs += p;
                }
                #pragma unroll
                for (int off = 1; off < 16; off <<= 1)
                    rs += __shfl_xor_sync(0xffffffffu, rs, off);

                l[i] = l[i] * alpha + rs;
                unsigned long long a2 = pk2(alpha, alpha);
                #pragma unroll
                for (int j = 0; j < 4; j++) MUL2(o2[i][j], o2[i][j], a2);
            }
            __syncthreads();

            // ---- O += P V, packed along kv ----
            #pragma unroll 4
            for (int k4 = 0; k4 < 16; k4++) {
                float4 v0 = *reinterpret_cast<const float4*>(&Vs[k4 * 4 + 0][c0]);
                float4 v1 = *reinterpret_cast<const float4*>(&Vs[k4 * 4 + 1][c0]);
                float4 v2 = *reinterpret_cast<const float4*>(&Vs[k4 * 4 + 2][c0]);
                float4 v3 = *reinterpret_cast<const float4*>(&Vs[k4 * 4 + 3][c0]);
                ulonglong2 p2[4];
                #pragma unroll
                for (int i = 0; i < 4; i++)
                    p2[i] = *reinterpret_cast<const ulonglong2*>(&Ss[r0 + i][k4 * 4]);

                unsigned long long va0 = pk2(v0.x, v1.x), va1 = pk2(v2.x, v3.x);
                unsigned long long vb0 = pk2(v0.y, v1.y), vb1 = pk2(v2.y, v3.y);
                unsigned long long vc0 = pk2(v0.z, v1.z), vc1 = pk2(v2.z, v3.z);
                unsigned long long vd0 = pk2(v0.w, v1.w), vd1 = pk2(v2.w, v3.w);

                #pragma unroll
                for (int i = 0; i < 4; i++) {
                    FMA2(o2[i][0], p2[i].x, va0); FMA2(o2[i][0], p2[i].y, va1);
                    FMA2(o2[i][1], p2[i].x, vb0); FMA2(o2[i][1], p2[i].y, vb1);
                    FMA2(o2[i][2], p2[i].x, vc0); FMA2(o2[i][2], p2[i].y, vc1);
                    FMA2(o2[i][3], p2[i].x, vd0); FMA2(o2[i][3], p2[i].y, vd1);
                }
            }
            __syncthreads();
        }

        // epilogue
        float* Og = out + (size_t)(b * T_ + qt * 64) * DH_;
        #pragma unroll
        for (int i = 0; i < 4; i++) {
            float inv = 1.0f / l[i];
            float4 r;
            r.x = unpk_sum(o2[i][0]) * inv;
            r.y = unpk_sum(o2[i][1]) * inv;
            r.z = unpk_sum(o2[i][2]) * inv;
            r.w = unpk_sum(o2[i][3]) * inv;
            *reinterpret_cast<float4*>(&Og[(r0 + i) * DH_ + c0]) = r;
        }
    }
}

// ---------------------------------------------------------------------------
extern "C" void kernel_launch(void* const* d_in, const int* in_sizes, int n_in,
                              void* d_out, int out_size)
{
    const float* x  = (const float*)d_in[0];
    const float* Wq = (const float*)d_in[1];
    const float* Wk = (const float*)d_in[2];
    const float* Wv = (const float*)d_in[3];
    float* out = (float*)d_out;

    dim3 g1(NROW / 64, 3);
    proj_kernel<<<g1, 256>>>(x, Wq, Wk, Wv);

    size_t smem = (size_t)4 * 64 * SROW * sizeof(float);   // 69632 B
    cudaFuncSetAttribute(attn_kernel,
                         cudaFuncAttributeMaxDynamicSharedMemorySize,
                         (int)smem);
    attn_kernel<<<296, 256, smem>>>(out);
}

// round 3
// speedup vs baseline: 1.4223x; 1.4072x over previous
#include <cuda_runtime.h>
#include <math.h>

#define B_  4
#define T_  4096
#define D_  1024
#define DH_ 64
#define NROW (B_ * T_)
#define CH_ 16                         // kv tiles per chunk
#define NITEM 640                      // 4 * sum_qt ceil((qt+1)/16)

__device__ float g_Q[NROW * DH_];
__device__ float g_K[NROW * DH_];
__device__ float g_V[NROW * DH_];
__device__ unsigned int g_ctr;
// partial-result scratch: indexed by ((b*64+qt)*4 + chunk)
__device__ float g_po[256 * 4 * 4096];     // unnormalized O tiles
__device__ float g_pml[256 * 4 * 128];     // m[64], l[64] per partial

// ---- packed f32x2 helpers ----
#define FMA2(d, a, b) asm("fma.rn.f32x2 %0, %1, %2, %0;" : "+l"(d) : "l"(a), "l"(b))
#define MUL2(d, a, b) asm("mul.rn.f32x2 %0, %1, %2;" : "=l"(d) : "l"(a), "l"(b))

static __device__ __forceinline__ unsigned long long pk2(float a, float b) {
    unsigned long long r;
    asm("mov.b64 %0, {%1, %2};" : "=l"(r) : "f"(a), "f"(b));
    return r;
}
static __device__ __forceinline__ float unpk_sum(unsigned long long v) {
    float lo, hi;
    asm("mov.b64 {%0, %1}, %2;" : "=f"(lo), "=f"(hi) : "l"(v));
    return lo + hi;
}

// ---------------------------------------------------------------------------
// Kernel 1: QKV projection (unchanged from R2, known good)
// ---------------------------------------------------------------------------
__global__ __launch_bounds__(256) void proj_kernel(
    const float* __restrict__ x,
    const float* __restrict__ Wq,
    const float* __restrict__ Wk,
    const float* __restrict__ Wv)
{
    const int tile  = blockIdx.x;
    const int which = blockIdx.y;
    const float* W  = (which == 0) ? Wq : (which == 1) ? Wk : Wv;
    float* out      = (which == 0) ? g_Q : (which == 1) ? g_K : g_V;

    __shared__ float xs[64][34];
    __shared__ float ws[32][DH_];

    const int tid = threadIdx.x;
    const int tx = tid & 15, ty = tid >> 4;
    const int r0 = ty * 4, c0 = tx * 4;
    const int row_base = tile * 64;

    if (tile == 0 && which == 0 && tid == 0) g_ctr = 0;

    unsigned long long acc2[4][4];
    #pragma unroll
    for (int i = 0; i < 4; i++)
        #pragma unroll
        for (int j = 0; j < 4; j++) acc2[i][j] = 0ull;

    for (int k0 = 0; k0 < D_; k0 += 32) {
        #pragma unroll
        for (int p = tid; p < 512; p += 256) {
            int r = p >> 3, c4 = (p & 7) * 4;
            float4 v = *reinterpret_cast<const float4*>(
                &x[(size_t)(row_base + r) * D_ + k0 + c4]);
            xs[r][c4 + 0] = v.x; xs[r][c4 + 1] = v.y;
            xs[r][c4 + 2] = v.z; xs[r][c4 + 3] = v.w;
        }
        #pragma unroll
        for (int p = tid; p < 512; p += 256) {
            int kr = p >> 4, c4 = (p & 15) * 4;
            *reinterpret_cast<float4*>(&ws[kr][c4]) =
                *reinterpret_cast<const float4*>(&W[(size_t)(k0 + kr) * DH_ + c4]);
        }
        __syncthreads();

        #pragma unroll 4
        for (int kp = 0; kp < 16; kp++) {
            unsigned long long a2[4];
            #pragma unroll
            for (int i = 0; i < 4; i++)
                a2[i] = *reinterpret_cast<const unsigned long long*>(&xs[r0 + i][kp * 2]);
            float4 wa = *reinterpret_cast<const float4*>(&ws[kp * 2][c0]);
            float4 wb = *reinterpret_cast<const float4*>(&ws[kp * 2 + 1][c0]);
            unsigned long long b2[4];
            b2[0] = pk2(wa.x, wb.x); b2[1] = pk2(wa.y, wb.y);
            b2[2] = pk2(wa.z, wb.z); b2[3] = pk2(wa.w, wb.w);
            #pragma unroll
            for (int i = 0; i < 4; i++)
                #pragma unroll
                for (int j = 0; j < 4; j++)
                    FMA2(acc2[i][j], a2[i], b2[j]);
        }
        __syncthreads();
    }

    #pragma unroll
    for (int i = 0; i < 4; i++) {
        float4 r;
        r.x = unpk_sum(acc2[i][0]); r.y = unpk_sum(acc2[i][1]);
        r.z = unpk_sum(acc2[i][2]); r.w = unpk_sum(acc2[i][3]);
        *reinterpret_cast<float4*>(&out[(size_t)(row_base + r0 + i) * DH_ + c0]) = r;
    }
}

// ---------------------------------------------------------------------------
// Kernel 2: persistent causal flash attention with KV-SPLIT work items.
// Item = (b, qt, chunk): chunk covers kv tiles [ch*16, min(ch*16+16, qt+1)).
// Single-chunk q-tiles (qt<16) write output directly; others write partials.
// ---------------------------------------------------------------------------
#define SROW 68

__global__ __launch_bounds__(256, 2) void attn_kernel(float* __restrict__ out)
{
    extern __shared__ float sm[];
    float (*Qs)[SROW] = (float(*)[SROW])(sm);
    float (*Ks)[SROW] = (float(*)[SROW])(sm + 64 * SROW);
    float (*Vs)[SROW] = (float(*)[SROW])(sm + 2 * 64 * SROW);
    float (*Ss)[SROW] = (float(*)[SROW])(sm + 3 * 64 * SROW);
    __shared__ int s_item;

    const int tid = threadIdx.x;
    const int tx = tid & 15, ty = tid >> 4;
    const int r0 = ty * 4, c0 = tx * 4;
    const float scale = 0.03125f;   // 1024^-0.5

    for (;;) {
        if (tid == 0) s_item = atomicAdd(&g_ctr, 1);
        __syncthreads();
        const int n = s_item;
        if (n >= NITEM) return;
        const int b = n & 3;
        int idx = n >> 2;                  // 0..159, ascending => qt descending
        int qt = 63, rem = idx;
        while (rem >= ((qt + 16) >> 4)) { rem -= (qt + 16) >> 4; qt--; }
        const int ch = rem;
        const int nc = (qt + 16) >> 4;
        const int t0 = ch * CH_;
        const int t1 = (t0 + CH_ < qt + 1) ? (t0 + CH_) : (qt + 1);

        // load Q tile
        const float* Qg = g_Q + (size_t)(b * T_ + qt * 64) * DH_;
        #pragma unroll
        for (int p = tid; p < 1024; p += 256) {
            int r = p >> 4, c4 = (p & 15) * 4;
            float4 v = *reinterpret_cast<const float4*>(&Qg[r * DH_ + c4]);
            Qs[r][c4 + 0] = v.x; Qs[r][c4 + 1] = v.y;
            Qs[r][c4 + 2] = v.z; Qs[r][c4 + 3] = v.w;
        }

        float m[4], l[4];
        unsigned long long o2[4][4];
        #pragma unroll
        for (int i = 0; i < 4; i++) {
            m[i] = -INFINITY; l[i] = 0.f;
            #pragma unroll
            for (int j = 0; j < 4; j++) o2[i][j] = 0ull;
        }
        __syncthreads();

        for (int t = t0; t < t1; t++) {
            const float* Kg = g_K + (size_t)(b * T_ + t * 64) * DH_;
            const float* Vg = g_V + (size_t)(b * T_ + t * 64) * DH_;
            #pragma unroll
            for (int p = tid; p < 1024; p += 256) {
                int r = p >> 4, c4 = (p & 15) * 4;
                float4 v = *reinterpret_cast<const float4*>(&Kg[r * DH_ + c4]);
                Ks[r][c4 + 0] = v.x; Ks[r][c4 + 1] = v.y;
                Ks[r][c4 + 2] = v.z; Ks[r][c4 + 3] = v.w;
                float4 w = *reinterpret_cast<const float4*>(&Vg[r * DH_ + c4]);
                Vs[r][c4 + 0] = w.x; Vs[r][c4 + 1] = w.y;
                Vs[r][c4 + 2] = w.z; Vs[r][c4 + 3] = w.w;
            }
            __syncthreads();

            // S = Q K^T (packed along dh)
            unsigned long long s2[4][4];
            #pragma unroll
            for (int i = 0; i < 4; i++)
                #pragma unroll
                for (int j = 0; j < 4; j++) s2[i][j] = 0ull;

            #pragma unroll 4
            for (int k4 = 0; k4 < 16; k4++) {
                ulonglong2 q2[4], k2[4];
                #pragma unroll
                for (int i = 0; i < 4; i++)
                    q2[i] = *reinterpret_cast<const ulonglong2*>(&Qs[r0 + i][k4 * 4]);
                #pragma unroll
                for (int j = 0; j < 4; j++)
                    k2[j] = *reinterpret_cast<const ulonglong2*>(&Ks[tx + 16 * j][k4 * 4]);
                #pragma unroll
                for (int i = 0; i < 4; i++)
                    #pragma unroll
                    for (int j = 0; j < 4; j++) {
                        FMA2(s2[i][j], q2[i].x, k2[j].x);
                        FMA2(s2[i][j], q2[i].y, k2[j].y);
                    }
            }

            const bool diag = (t == qt);

            // online softmax
            #pragma unroll
            for (int i = 0; i < 4; i++) {
                float sv[4];
                float mt = -INFINITY;
                #pragma unroll
                for (int j = 0; j < 4; j++) {
                    float v = unpk_sum(s2[i][j]) * scale;
                    if (diag && (tx + 16 * j) > (r0 + i)) v = -1e30f;
                    sv[j] = v;
                    mt = fmaxf(mt, v);
                }
                #pragma unroll
                for (int off = 1; off < 16; off <<= 1)
                    mt = fmaxf(mt, __shfl_xor_sync(0xffffffffu, mt, off));

                float mn    = fmaxf(m[i], mt);
                float alpha = __expf(m[i] - mn);
                m[i] = mn;

                float rs = 0.f;
                #pragma unroll
                for (int j = 0; j < 4; j++) {
                    float p = __expf(sv[j] - mn);
                    Ss[r0 + i][tx + 16 * j] = p;
                    rs += p;
                }
                #pragma unroll
                for (int off = 1; off < 16; off <<= 1)
                    rs += __shfl_xor_sync(0xffffffffu, rs, off);

                l[i] = l[i] * alpha + rs;
                unsigned long long a2 = pk2(alpha, alpha);
                #pragma unroll
                for (int j = 0; j < 4; j++) MUL2(o2[i][j], o2[i][j], a2);
            }
            __syncthreads();

            // O += P V (packed along kv)
            #pragma unroll 4
            for (int k4 = 0; k4 < 16; k4++) {
                float4 v0 = *reinterpret_cast<const float4*>(&Vs[k4 * 4 + 0][c0]);
                float4 v1 = *reinterpret_cast<const float4*>(&Vs[k4 * 4 + 1][c0]);
                float4 v2 = *reinterpret_cast<const float4*>(&Vs[k4 * 4 + 2][c0]);
                float4 v3 = *reinterpret_cast<const float4*>(&Vs[k4 * 4 + 3][c0]);
                ulonglong2 p2[4];
                #pragma unroll
                for (int i = 0; i < 4; i++)
                    p2[i] = *reinterpret_cast<const ulonglong2*>(&Ss[r0 + i][k4 * 4]);

                unsigned long long va0 = pk2(v0.x, v1.x), va1 = pk2(v2.x, v3.x);
                unsigned long long vb0 = pk2(v0.y, v1.y), vb1 = pk2(v2.y, v3.y);
                unsigned long long vc0 = pk2(v0.z, v1.z), vc1 = pk2(v2.z, v3.z);
                unsigned long long vd0 = pk2(v0.w, v1.w), vd1 = pk2(v2.w, v3.w);

                #pragma unroll
                for (int i = 0; i < 4; i++) {
                    FMA2(o2[i][0], p2[i].x, va0); FMA2(o2[i][0], p2[i].y, va1);
                    FMA2(o2[i][1], p2[i].x, vb0); FMA2(o2[i][1], p2[i].y, vb1);
                    FMA2(o2[i][2], p2[i].x, vc0); FMA2(o2[i][2], p2[i].y, vc1);
                    FMA2(o2[i][3], p2[i].x, vd0); FMA2(o2[i][3], p2[i].y, vd1);
                }
            }
            __syncthreads();
        }

        // epilogue: direct write (single chunk) or partial scratch
        if (nc == 1) {
            float* Og = out + (size_t)(b * T_ + qt * 64) * DH_;
            #pragma unroll
            for (int i = 0; i < 4; i++) {
                float inv = 1.0f / l[i];
                float4 r;
                r.x = unpk_sum(o2[i][0]) * inv;
                r.y = unpk_sum(o2[i][1]) * inv;
                r.z = unpk_sum(o2[i][2]) * inv;
                r.w = unpk_sum(o2[i][3]) * inv;
                *reinterpret_cast<float4*>(&Og[(r0 + i) * DH_ + c0]) = r;
            }
        } else {
            const int pidx = (b * 64 + qt) * 4 + ch;
            float* po = g_po + (size_t)pidx * 4096;
            #pragma unroll
            for (int i = 0; i < 4; i++) {
                float4 r;
                r.x = unpk_sum(o2[i][0]);
                r.y = unpk_sum(o2[i][1]);
                r.z = unpk_sum(o2[i][2]);
                r.w = unpk_sum(o2[i][3]);
                *reinterpret_cast<float4*>(&po[(r0 + i) * 64 + c0]) = r;
                if (tx == 0) {
                    g_pml[pidx * 128 + (r0 + i)]      = m[i];
                    g_pml[pidx * 128 + 64 + (r0 + i)] = l[i];
                }
            }
        }
    }
}

// ---------------------------------------------------------------------------
// Kernel 3: merge partials for qt >= 16. Block = one (b, qt).
// ---------------------------------------------------------------------------
__global__ __launch_bounds__(256) void merge_kernel(float* __restrict__ out)
{
    const int bid = blockIdx.x;             // 0..191
    const int b  = bid & 3;
    const int qt = 16 + (bid >> 2);
    const int nc = (qt + 16) >> 4;          // 2..4
    const int tid = threadIdx.x;
    const int r  = tid >> 2;                // q row within tile
    const int cg = (tid & 3) << 4;          // 16-col group

    const int base = (b * 64 + qt) * 4;

    float mv[4], lv[4];
    float ms = -INFINITY;
    #pragma unroll
    for (int c = 0; c < 4; c++)
        if (c < nc) {
            mv[c] = g_pml[(base + c) * 128 + r];
            lv[c] = g_pml[(base + c) * 128 + 64 + r];
            ms = fmaxf(ms, mv[c]);
        }

    float acc[16];
    #pragma unroll
    for (int j = 0; j < 16; j++) acc[j] = 0.f;
    float lsum = 0.f;

    #pragma unroll
    for (int c = 0; c < 4; c++)
        if (c < nc) {
            float w = __expf(mv[c] - ms);
            lsum += lv[c] * w;
            const float* po = g_po + (size_t)(base + c) * 4096 + r * 64 + cg;
            #pragma unroll
            for (int j4 = 0; j4 < 4; j4++) {
                float4 v = *reinterpret_cast<const float4*>(po + j4 * 4);
                acc[j4 * 4 + 0] = fmaf(v.x, w, acc[j4 * 4 + 0]);
                acc[j4 * 4 + 1] = fmaf(v.y, w, acc[j4 * 4 + 1]);
                acc[j4 * 4 + 2] = fmaf(v.z, w, acc[j4 * 4 + 2]);
                acc[j4 * 4 + 3] = fmaf(v.w, w, acc[j4 * 4 + 3]);
            }
        }

    const float inv = 1.0f / lsum;
    float* og = out + (size_t)(b * T_ + qt * 64 + r) * DH_ + cg;
    #pragma unroll
    for (int j4 = 0; j4 < 4; j4++) {
        float4 v;
        v.x = acc[j4 * 4 + 0] * inv;
        v.y = acc[j4 * 4 + 1] * inv;
        v.z = acc[j4 * 4 + 2] * inv;
        v.w = acc[j4 * 4 + 3] * inv;
        *reinterpret_cast<float4*>(og + j4 * 4) = v;
    }
}

// ---------------------------------------------------------------------------
extern "C" void kernel_launch(void* const* d_in, const int* in_sizes, int n_in,
                              void* d_out, int out_size)
{
    const float* x  = (const float*)d_in[0];
    const float* Wq = (const float*)d_in[1];
    const float* Wk = (const float*)d_in[2];
    const float* Wv = (const float*)d_in[3];
    float* out = (float*)d_out;

    dim3 g1(NROW / 64, 3);
    proj_kernel<<<g1, 256>>>(x, Wq, Wk, Wv);

    size_t smem = (size_t)4 * 64 * SROW * sizeof(float);   // 69632 B
    cudaFuncSetAttribute(attn_kernel,
                         cudaFuncAttributeMaxDynamicSharedMemorySize,
                         (int)smem);
    attn_kernel<<<296, 256, smem>>>(out);

    merge_kernel<<<192, 256>>>(out);
}